// round 7
// baseline (speedup 1.0000x reference)
#include <cuda_runtime.h>
#include <cuda_bf16.h>
#include <cstdint>

#define HDIM 2048
#define MDIM 1408
#define NEXP 8
#define NTOK 1024

// ---------------- device scratch ----------------
__device__ __nv_bfloat16 g_xhi[NTOK * HDIM];
__device__ __nv_bfloat16 g_xlo[NTOK * HDIM];
__device__ __nv_bfloat16 g_ahi[(NEXP + 1) * NTOK * MDIM];
__device__ __nv_bfloat16 g_alo[(NEXP + 1) * NTOK * MDIM];
// weight bf16 hi/lo planes; slot NEXP = shared expert
__device__ __nv_bfloat16 g_wghi[(NEXP + 1) * MDIM * HDIM];
__device__ __nv_bfloat16 g_wglo[(NEXP + 1) * MDIM * HDIM];
__device__ __nv_bfloat16 g_wuhi[(NEXP + 1) * MDIM * HDIM];
__device__ __nv_bfloat16 g_wulo[(NEXP + 1) * MDIM * HDIM];
__device__ __nv_bfloat16 g_wdhi[(NEXP + 1) * HDIM * MDIM];
__device__ __nv_bfloat16 g_wdlo[(NEXP + 1) * HDIM * MDIM];
__device__ int   g_tok[NEXP * NTOK];
__device__ float g_wt[NEXP * NTOK];
__device__ int   g_cnt[NEXP];
__device__ float g_pisum[NEXP];

// ---------------- helpers ----------------
__device__ __forceinline__ uint32_t smem_u32(const void* p) {
    uint32_t a;
    asm("{ .reg .u64 t; cvta.to.shared.u64 t, %1; cvt.u32.u64 %0, t; }" : "=r"(a) : "l"(p));
    return a;
}
__device__ __forceinline__ void cp16(uint32_t dst, const void* src) {
    asm volatile("cp.async.cg.shared.global [%0], [%1], 16;" :: "r"(dst), "l"(src));
}
#define CP_COMMIT() asm volatile("cp.async.commit_group;" ::: "memory")
#define CP_WAIT2()  asm volatile("cp.async.wait_group 2;" ::: "memory")

#define LDSM4(r, addr)                                                                       \
    asm volatile("ldmatrix.sync.aligned.m8n8.x4.shared.b16 {%0,%1,%2,%3}, [%4];"             \
                 : "=r"((r)[0]), "=r"((r)[1]), "=r"((r)[2]), "=r"((r)[3]) : "r"(addr))
#define LDSM2(r, addr)                                                                       \
    asm volatile("ldmatrix.sync.aligned.m8n8.x2.shared.b16 {%0,%1}, [%2];"                   \
                 : "=r"((r)[0]), "=r"((r)[1]) : "r"(addr))
#define MMA(c, a, b)                                                                         \
    asm volatile("mma.sync.aligned.m16n8k16.row.col.f32.bf16.bf16.f32 "                      \
                 "{%0,%1,%2,%3},{%4,%5,%6,%7},{%8,%9},{%0,%1,%2,%3};"                        \
                 : "+f"((c)[0]), "+f"((c)[1]), "+f"((c)[2]), "+f"((c)[3])                    \
                 : "r"((a)[0]), "r"((a)[1]), "r"((a)[2]), "r"((a)[3]), "r"((b)[0]), "r"((b)[1]))

__device__ __forceinline__ void split2(float a, float b, uint32_t& hi, uint32_t& lo) {
    __nv_bfloat16 ha = __float2bfloat16(a), hb = __float2bfloat16(b);
    float ra = a - __bfloat162float(ha), rb = b - __bfloat162float(hb);
    __nv_bfloat16 la = __float2bfloat16(ra), lb = __float2bfloat16(rb);
    __nv_bfloat162 hp; hp.x = ha; hp.y = hb;
    __nv_bfloat162 lp; lp.x = la; lp.y = lb;
    hi = *reinterpret_cast<uint32_t*>(&hp);
    lo = *reinterpret_cast<uint32_t*>(&lp);
}

#define ROW16 48   // 16 bf16 (32B) + 16B pad -> conflict-free ldmatrix

// ---------------- init / conversions ----------------
__global__ void zero_kernel(float* __restrict__ y) {
    int i = blockIdx.x * blockDim.x + threadIdx.x;
    if (i < NTOK * HDIM) y[i] = 0.f;
    if (i < NEXP) { g_cnt[i] = 0; g_pisum[i] = 0.f; }
}

__global__ void xconv_kernel(const float* __restrict__ x) {
    int i = blockIdx.x * blockDim.x + threadIdx.x;
    if (i < NTOK * HDIM) {
        float v = x[i];
        __nv_bfloat16 h = __float2bfloat16(v);
        __nv_bfloat16 l = __float2bfloat16(v - __bfloat162float(h));
        g_xhi[i] = h; g_xlo[i] = l;
    }
}

// fp32 -> bf16 hi/lo planes; destination selected device-side
__global__ __launch_bounds__(256)
void wconv_kernel(const float4* __restrict__ src, int which, size_t dstOff, int n4) {
    int i = blockIdx.x * blockDim.x + threadIdx.x;
    if (i >= n4) return;
    __nv_bfloat16 *hb, *lb;
    if (which == 0)      { hb = g_wghi; lb = g_wglo; }
    else if (which == 1) { hb = g_wuhi; lb = g_wulo; }
    else                 { hb = g_wdhi; lb = g_wdlo; }
    uint2* hp = (uint2*)(hb + dstOff);
    uint2* lp = (uint2*)(lb + dstOff);
    float4 v = src[i];
    uint2 h, l;
    split2(v.x, v.y, h.x, l.x);
    split2(v.z, v.w, h.y, l.y);
    hp[i] = h; lp[i] = l;
}

// ---------------- gate ----------------
__global__ __launch_bounds__(256)
void gate_kernel(const float* __restrict__ x, const float* __restrict__ gw) {
    const int t = blockIdx.x;
    const float* xr = x + (size_t)t * HDIM;
    float acc[NEXP];
#pragma unroll
    for (int e = 0; e < NEXP; e++) acc[e] = 0.f;
    for (int h = threadIdx.x; h < HDIM; h += 256) {
        float xv = xr[h];
#pragma unroll
        for (int e = 0; e < NEXP; e++) acc[e] = fmaf(xv, gw[e * HDIM + h], acc[e]);
    }
#pragma unroll
    for (int e = 0; e < NEXP; e++)
        for (int o = 16; o > 0; o >>= 1) acc[e] += __shfl_down_sync(0xffffffffu, acc[e], o);

    __shared__ float red[8][NEXP];
    int warp = threadIdx.x >> 5, lane = threadIdx.x & 31;
    if (lane == 0) {
#pragma unroll
        for (int e = 0; e < NEXP; e++) red[warp][e] = acc[e];
    }
    __syncthreads();
    if (threadIdx.x == 0) {
        float lg[NEXP];
#pragma unroll
        for (int e = 0; e < NEXP; e++) {
            float s = 0.f;
            for (int w = 0; w < 8; w++) s += red[w][e];
            lg[e] = s;
        }
        float mx = lg[0];
#pragma unroll
        for (int e = 1; e < NEXP; e++) mx = fmaxf(mx, lg[e]);
        float p[NEXP]; float den = 0.f;
#pragma unroll
        for (int e = 0; e < NEXP; e++) { p[e] = __expf(lg[e] - mx); den += p[e]; }
#pragma unroll
        for (int e = 0; e < NEXP; e++) p[e] /= den;
#pragma unroll
        for (int e = 0; e < NEXP; e++) atomicAdd(&g_pisum[e], p[e]);
        int i1 = 0;
#pragma unroll
        for (int e = 1; e < NEXP; e++) if (p[e] > p[i1]) i1 = e;
        int i2 = -1;
#pragma unroll
        for (int e = 0; e < NEXP; e++) {
            if (e == i1) continue;
            if (i2 < 0 || p[e] > p[i2]) i2 = e;
        }
        float w1 = p[i1], w2 = p[i2];
        float s2 = w1 + w2 + 1e-20f;
        w1 /= s2; w2 /= s2;
        int pos1 = atomicAdd(&g_cnt[i1], 1);
        g_tok[i1 * NTOK + pos1] = t; g_wt[i1 * NTOK + pos1] = w1;
        int pos2 = atomicAdd(&g_cnt[i2], 1);
        g_tok[i2 * NTOK + pos2] = t; g_wt[i2 * NTOK + pos2] = w2;
    }
}

// =======================================================================
// gateup: act = silu(X Wg^T) * (X Wu^T)  tile 128x64, K chunk 16, 4-stage
// grid z: 0..7 routed experts, 8 = shared expert
// =======================================================================
#define GU_STG  24576
#define GU_AHI  0
#define GU_ALO  6144
#define GU_BGH  12288
#define GU_BGL  15360
#define GU_BUH  18432
#define GU_BUL  21504
#define GU_TOK  (4 * GU_STG)
#define GU_SM   (GU_TOK + 512)

__global__ __launch_bounds__(256, 2)
void gateup_mma() {
    extern __shared__ __align__(128) char sm[];
    const int z = blockIdx.z;
    const bool SH = (z == NEXP);
    const int nrows = SH ? NTOK : g_cnt[z];
    const int row0 = blockIdx.x * 128;
    if (row0 >= nrows) return;
    const int n0 = blockIdx.y * 64;

    const int tid = threadIdx.x, wid = tid >> 5, lane = tid & 31;
    int* toks = (int*)(sm + GU_TOK);
    if (tid < 128) {
        int r = row0 + tid;
        toks[tid] = (r < nrows) ? (SH ? r : g_tok[z * NTOK + r]) : 0;
    }
    __syncthreads();

    const uint32_t sb = smem_u32(sm);

    // A cp mapping: 2 thr/row (seg 16B), one cp16 per plane
    const int arow = tid >> 1, aseg = tid & 1;
    const __nv_bfloat16* aph = g_xhi + (size_t)toks[arow] * HDIM + aseg * 8;
    const __nv_bfloat16* apl = g_xlo + (size_t)toks[arow] * HDIM + aseg * 8;
    const uint32_t aDH = sb + GU_AHI + arow * ROW16 + aseg * 16;
    const uint32_t aDL = sb + GU_ALO + arow * ROW16 + aseg * 16;

    // B cp mapping: plane = tid>>6 (gh, gl, uh, ul), row = tid&63, both segs
    const int bpl = tid >> 6, brow = tid & 63;
    const __nv_bfloat16* bsrc;
    uint32_t bplaneOff;
    {
        const size_t bOff = ((size_t)z * MDIM + n0 + brow) * HDIM;
        if (bpl == 0)      { bsrc = g_wghi + bOff; bplaneOff = GU_BGH; }
        else if (bpl == 1) { bsrc = g_wglo + bOff; bplaneOff = GU_BGL; }
        else if (bpl == 2) { bsrc = g_wuhi + bOff; bplaneOff = GU_BUH; }
        else               { bsrc = g_wulo + bOff; bplaneOff = GU_BUL; }
    }
    const uint32_t bD = sb + bplaneOff + brow * ROW16;

#define GU_CP(c) do { uint32_t o = ((c) & 3) * GU_STG; size_t ko = (size_t)(c) * 16;  \
    cp16(aDH + o, aph + ko);  cp16(aDL + o, apl + ko);                                \
    cp16(bD + o,      bsrc + ko);                                                     \
    cp16(bD + o + 16, bsrc + ko + 8); } while (0)

    // compute fragment bases (warp grid 2m x 4n; warp tile 64x16)
    const int wm = wid & 1, wn = wid >> 1;
    const uint32_t aOffL = (lane & 15) * ROW16 + (lane >> 4) * 16;
    const uint32_t bOffL = (lane & 7) * ROW16 + ((lane >> 3) & 1) * 16;
    const uint32_t aHiB = sb + GU_AHI + (wm * 64) * ROW16 + aOffL;
    const uint32_t aLoB = sb + GU_ALO + (wm * 64) * ROW16 + aOffL;
    const uint32_t bGH = sb + GU_BGH + (wn * 16) * ROW16 + bOffL;
    const uint32_t bGL = sb + GU_BGL + (wn * 16) * ROW16 + bOffL;
    const uint32_t bUH = sb + GU_BUH + (wn * 16) * ROW16 + bOffL;
    const uint32_t bUL = sb + GU_BUL + (wn * 16) * ROW16 + bOffL;

    float accg[4][2][4] = {}, accu[4][2][4] = {};

    const int NC = HDIM / 16;
    GU_CP(0); CP_COMMIT();
    GU_CP(1); CP_COMMIT();
    GU_CP(2); CP_COMMIT();

    for (int c = 0; c < NC; c++) {
        const uint32_t so = (c & 3) * GU_STG;
        CP_WAIT2();
        __syncthreads();
        if (c + 3 < NC) GU_CP(c + 3);
        CP_COMMIT();   // commit every iter (possibly empty) to keep wait_group invariant

        uint32_t ah[4][4], al[4][4];
#pragma unroll
        for (int i = 0; i < 4; i++) {
            LDSM4(ah[i], aHiB + so + i * (16 * ROW16));
            LDSM4(al[i], aLoB + so + i * (16 * ROW16));
        }
        uint32_t bgh[2][2], bgl[2][2], buh[2][2], bul[2][2];
#pragma unroll
        for (int j = 0; j < 2; j++) {
            LDSM2(bgh[j], bGH + so + j * (8 * ROW16));
            LDSM2(bgl[j], bGL + so + j * (8 * ROW16));
            LDSM2(buh[j], bUH + so + j * (8 * ROW16));
            LDSM2(bul[j], bUL + so + j * (8 * ROW16));
        }
#pragma unroll
        for (int i = 0; i < 4; i++)
#pragma unroll
            for (int j = 0; j < 2; j++) {
                MMA(accg[i][j], ah[i], bgh[j]);
                MMA(accg[i][j], ah[i], bgl[j]);
                MMA(accg[i][j], al[i], bgh[j]);
                MMA(accu[i][j], ah[i], buh[j]);
                MMA(accu[i][j], ah[i], bul[j]);
                MMA(accu[i][j], al[i], buh[j]);
            }
    }

    // epilogue: silu(g)*u -> bf16 planes
    const int mrow = wm * 64 + (lane >> 2);
    const int col0 = n0 + wn * 16 + (lane & 3) * 2;
#pragma unroll
    for (int i = 0; i < 4; i++)
#pragma unroll
        for (int j = 0; j < 2; j++) {
            int col = col0 + j * 8;
#pragma unroll
            for (int half = 0; half < 2; half++) {
                int r = row0 + mrow + i * 16 + half * 8;
                if (r < nrows) {
                    float gv0 = accg[i][j][half * 2],     uv0 = accu[i][j][half * 2];
                    float gv1 = accg[i][j][half * 2 + 1], uv1 = accu[i][j][half * 2 + 1];
                    float a0 = (gv0 / (1.f + __expf(-gv0))) * uv0;
                    float a1 = (gv1 / (1.f + __expf(-gv1))) * uv1;
                    uint32_t hi, lo;
                    split2(a0, a1, hi, lo);
                    size_t idx = ((size_t)z * NTOK + r) * MDIM + col;
                    *(uint32_t*)(g_ahi + idx) = hi;
                    *(uint32_t*)(g_alo + idx) = lo;
                }
            }
        }
#undef GU_CP
}

// =======================================================================
// down: y[tok] += w * (act @ Wd^T)  tile 128x128, K chunk 16, 4-stage
// =======================================================================
#define DN_STG  24576
#define DN_AHI  0
#define DN_ALO  6144
#define DN_BH   12288
#define DN_BL   18432
#define DN_TOK  (4 * DN_STG)
#define DN_WTS  (DN_TOK + 512)
#define DN_SM   (DN_WTS + 512)

__global__ __launch_bounds__(256, 2)
void down_mma(float* __restrict__ y) {
    extern __shared__ __align__(128) char sm[];
    const int z = blockIdx.z;
    const bool SH = (z == NEXP);
    const int nrows = SH ? NTOK : g_cnt[z];
    const int row0 = blockIdx.x * 128;
    if (row0 >= nrows) return;
    const int h0 = blockIdx.y * 128;

    const int tid = threadIdx.x, wid = tid >> 5, lane = tid & 31;
    int* toks = (int*)(sm + DN_TOK);
    float* wts = (float*)(sm + DN_WTS);
    if (tid < 128) {
        int r = row0 + tid;
        if (r < nrows) {
            toks[tid] = SH ? r : g_tok[z * NTOK + r];
            wts[tid]  = SH ? 1.f : g_wt[z * NTOK + r];
        } else { toks[tid] = 0; wts[tid] = 0.f; }
    }
    __syncthreads();

    const uint32_t sb = smem_u32(sm);

    // A cp mapping: 2 thr/row, one cp16 per plane
    const int arow = tid >> 1, aseg = tid & 1;
    const __nv_bfloat16* aph = g_ahi + ((size_t)z * NTOK + row0 + arow) * MDIM + aseg * 8;
    const __nv_bfloat16* apl = g_alo + ((size_t)z * NTOK + row0 + arow) * MDIM + aseg * 8;
    const uint32_t aDH = sb + DN_AHI + arow * ROW16 + aseg * 16;
    const uint32_t aDL = sb + DN_ALO + arow * ROW16 + aseg * 16;

    // B cp mapping: plane = tid>>7 (hi, lo), row = tid&127, both segs
    const int bpl = tid >> 7, brow = tid & 127;
    const size_t bOff = ((size_t)z * HDIM + h0 + brow) * MDIM;
    const __nv_bfloat16* bsrc = (bpl == 0) ? (g_wdhi + bOff) : (g_wdlo + bOff);
    const uint32_t bD = sb + (bpl == 0 ? DN_BH : DN_BL) + brow * ROW16;

#define DN_CP(c) do { uint32_t o = ((c) & 3) * DN_STG; size_t ko = (size_t)(c) * 16;  \
    cp16(aDH + o, aph + ko);  cp16(aDL + o, apl + ko);                                \
    cp16(bD + o,      bsrc + ko);                                                     \
    cp16(bD + o + 16, bsrc + ko + 8); } while (0)

    const int wm = wid & 1, wn = wid >> 1;   // warp tile 64x32
    const uint32_t aOffL = (lane & 15) * ROW16 + (lane >> 4) * 16;
    const uint32_t bOffL = (lane & 7) * ROW16 + ((lane >> 3) & 1) * 16;
    const uint32_t aHiB = sb + DN_AHI + (wm * 64) * ROW16 + aOffL;
    const uint32_t aLoB = sb + DN_ALO + (wm * 64) * ROW16 + aOffL;
    const uint32_t bHB = sb + DN_BH + (wn * 32) * ROW16 + bOffL;
    const uint32_t bLB = sb + DN_BL + (wn * 32) * ROW16 + bOffL;

    float acc[4][4][4] = {};

    const int NC = MDIM / 16;
    DN_CP(0); CP_COMMIT();
    DN_CP(1); CP_COMMIT();
    DN_CP(2); CP_COMMIT();

    for (int c = 0; c < NC; c++) {
        const uint32_t so = (c & 3) * DN_STG;
        CP_WAIT2();
        __syncthreads();
        if (c + 3 < NC) DN_CP(c + 3);
        CP_COMMIT();

        uint32_t ah[4][4], al[4][4];
#pragma unroll
        for (int i = 0; i < 4; i++) {
            LDSM4(ah[i], aHiB + so + i * (16 * ROW16));
            LDSM4(al[i], aLoB + so + i * (16 * ROW16));
        }
        uint32_t bh[4][2], bl[4][2];
#pragma unroll
        for (int j = 0; j < 4; j++) {
            LDSM2(bh[j], bHB + so + j * (8 * ROW16));
            LDSM2(bl[j], bLB + so + j * (8 * ROW16));
        }
#pragma unroll
        for (int i = 0; i < 4; i++)
#pragma unroll
            for (int j = 0; j < 4; j++) {
                MMA(acc[i][j], ah[i], bh[j]);
                MMA(acc[i][j], ah[i], bl[j]);
                MMA(acc[i][j], al[i], bh[j]);
            }
    }

    // epilogue: weighted atomic scatter
    const int mrow = wm * 64 + (lane >> 2);
    const int col0 = h0 + wn * 32 + (lane & 3) * 2;
#pragma unroll
    for (int i = 0; i < 4; i++)
#pragma unroll
        for (int half = 0; half < 2; half++) {
            int rl = mrow + i * 16 + half * 8;
            int r = row0 + rl;
            if (r < nrows) {
                float w = wts[rl];
                int tok = toks[rl];
                float* yp = y + (size_t)tok * HDIM;
#pragma unroll
                for (int j = 0; j < 4; j++) {
                    int col = col0 + j * 8;
                    atomicAdd(&yp[col],     acc[i][j][half * 2]     * w);
                    atomicAdd(&yp[col + 1], acc[i][j][half * 2 + 1] * w);
                }
            }
        }
#undef DN_CP
}

// ---------------- aux loss ----------------
__global__ void aux_kernel(float* __restrict__ p) {
    float a = 0.f;
#pragma unroll
    for (int e = 0; e < NEXP; e++) {
        float ce = (float)g_cnt[e] * ((float)NEXP / (float)(NTOK * 2));
        float pi = g_pisum[e] / (float)NTOK;
        a += ce * pi;
    }
    *p = a * 0.001f;
}

// ---------------- launch ----------------
extern "C" void kernel_launch(void* const* d_in, const int* in_sizes, int n_in,
                              void* d_out, int out_size) {
    (void)in_sizes; (void)n_in;
    const float* x   = (const float*)d_in[0];
    const float* gw  = (const float*)d_in[1];
    const float* wgt = (const float*)d_in[2];
    const float* wup = (const float*)d_in[3];
    const float* wdn = (const float*)d_in[4];
    const float* shg = (const float*)d_in[5];
    const float* shu = (const float*)d_in[6];
    const float* shd = (const float*)d_in[7];
    float* y = (float*)d_out;

    cudaFuncSetAttribute(gateup_mma, cudaFuncAttributeMaxDynamicSharedMemorySize, GU_SM);
    cudaFuncSetAttribute(down_mma,   cudaFuncAttributeMaxDynamicSharedMemorySize, DN_SM);

    zero_kernel<<<(NTOK * HDIM + 255) / 256, 256>>>(y);
    gate_kernel<<<NTOK, 256>>>(x, gw);
    xconv_kernel<<<(NTOK * HDIM + 255) / 256, 256>>>(x);

    const int NE4 = NEXP * MDIM * HDIM / 4;
    const int NS4 = MDIM * HDIM / 4;
    const size_t SOFF = (size_t)NEXP * MDIM * HDIM;
    wconv_kernel<<<(NE4 + 255) / 256, 256>>>((const float4*)wgt, 0, 0, NE4);
    wconv_kernel<<<(NE4 + 255) / 256, 256>>>((const float4*)wup, 1, 0, NE4);
    wconv_kernel<<<(NE4 + 255) / 256, 256>>>((const float4*)wdn, 2, 0, NE4);
    wconv_kernel<<<(NS4 + 255) / 256, 256>>>((const float4*)shg, 0, SOFF, NS4);
    wconv_kernel<<<(NS4 + 255) / 256, 256>>>((const float4*)shu, 1, SOFF, NS4);
    wconv_kernel<<<(NS4 + 255) / 256, 256>>>((const float4*)shd, 2, SOFF, NS4);

    gateup_mma<<<dim3(NTOK / 128, MDIM / 64, NEXP + 1), 256, GU_SM>>>();
    down_mma<<<dim3(NTOK / 128, HDIM / 128, NEXP + 1), 256, DN_SM>>>(y);

    if (out_size > NTOK * HDIM)
        aux_kernel<<<1, 1>>>(y + NTOK * HDIM);
}